// round 1
// baseline (speedup 1.0000x reference)
#include <cuda_runtime.h>
#include <cstdint>

#define SEQ   2048
#define BATCH 64
#define DIN   128
#define DH    256
#define G3    (3*DH)   // 768

// ---------------- scratch (device globals; no runtime allocation) ----------------
__device__ float g_gi[(size_t)SEQ * BATCH * G3];     // 402 MB  pre-computed input gates
__device__ float g_outs[(size_t)SEQ * BATCH * DH];   // 134 MB  all hidden states
__device__ float g_h[2][BATCH * DH];                 // double-buffered h
__device__ float g_scores[SEQ * BATCH];
__device__ float g_alpha[SEQ * BATCH];
__device__ unsigned int g_cnt[8];                    // per batch-group progress counters

// ---------------- helpers ----------------
__device__ __forceinline__ void fma2(unsigned long long& acc,
                                     unsigned long long a,
                                     unsigned long long b) {
    asm volatile("fma.rn.f32x2 %0, %1, %2, %0;" : "+l"(acc) : "l"(a), "l"(b));
}
__device__ __forceinline__ float2 u2f2(unsigned long long v) {
    float2 f;
    asm("mov.b64 {%0, %1}, %2;" : "=f"(f.x), "=f"(f.y) : "l"(v));
    return f;
}

// ---------------- init: reset progress counters (graph replays!) ----------------
__global__ void k_init() {
    if (threadIdx.x < 8) g_cnt[threadIdx.x] = 0u;
}

// ---------------- Phase 1: GI = mask(data) @ W_ih^T + b_ih ----------------
// M = SEQ*BATCH = 131072, N = 768, K = 128 (single K tile).
// 64x64 block tile, 256 threads, 4x4 micro-tile, f32x2 FMA pairs over k.
__global__ void __launch_bounds__(256) gi_gemm(const float* __restrict__ X,
                                               const float* __restrict__ Wih,
                                               const float* __restrict__ bih) {
    extern __shared__ float sm[];
    float* As = sm;               // 64 x 132
    float* Bs = sm + 64 * 132;    // 64 x 132
    __shared__ unsigned char maskf[64];

    const int tid = threadIdx.x;
    const int m0 = blockIdx.y * 64;
    const int n0 = blockIdx.x * 64;

    if (tid < 64) {
        float last = X[(size_t)(m0 + tid) * DIN + 127];
        maskf[tid] = (last > 0.0f) ? 1 : 0;
    }
    __syncthreads();

#pragma unroll
    for (int i = 0; i < 8; i++) {
        int f = tid + i * 256;       // 0..2047 float4 slots
        int r = f >> 5;              // row 0..63
        int kk = f & 31;             // float4 col 0..31
        float4 va = *(const float4*)&X[(size_t)(m0 + r) * DIN + kk * 4];
        if (maskf[r] && kk >= 8 && kk < 16) va = make_float4(0.f, 0.f, 0.f, 0.f);
        *(float4*)&As[r * 132 + kk * 4] = va;
        float4 vb = *(const float4*)&Wih[(size_t)(n0 + r) * DIN + kk * 4];
        *(float4*)&Bs[r * 132 + kk * 4] = vb;
    }
    __syncthreads();

    const int ty = tid >> 4;   // 0..15
    const int tx = tid & 15;   // 0..15

    unsigned long long acc[4][4];
#pragma unroll
    for (int i = 0; i < 4; i++)
#pragma unroll
        for (int j = 0; j < 4; j++) acc[i][j] = 0ull;

#pragma unroll 8
    for (int kk = 0; kk < 32; kk++) {
        ulonglong2 av[4], bv[4];
#pragma unroll
        for (int i = 0; i < 4; i++)
            av[i] = *(const ulonglong2*)&As[(ty * 4 + i) * 132 + kk * 4];
#pragma unroll
        for (int j = 0; j < 4; j++)
            bv[j] = *(const ulonglong2*)&Bs[(tx + 16 * j) * 132 + kk * 4];
#pragma unroll
        for (int i = 0; i < 4; i++)
#pragma unroll
            for (int j = 0; j < 4; j++) {
                fma2(acc[i][j], av[i].x, bv[j].x);
                fma2(acc[i][j], av[i].y, bv[j].y);
            }
    }

#pragma unroll
    for (int i = 0; i < 4; i++) {
        int m = m0 + ty * 4 + i;
#pragma unroll
        for (int j = 0; j < 4; j++) {
            int n = n0 + tx + 16 * j;
            float2 f = u2f2(acc[i][j]);
            g_gi[(size_t)m * G3 + n] = f.x + f.y + __ldg(&bih[n]);
        }
    }
}

// ---------------- Phase 2: persistent GRU recurrence ----------------
// Grid 128 = 8 batch-groups (Mb=8) x 16 unit-tiles (Ub=16). 384 threads:
// thread = (g, u, b): one 256-length dot per gate per (batch,unit).
// W_hh tile lives in SMEM for the whole kernel; h exchanged via L2 with
// per-group monotonic counters (only 16 blocks per sync domain).
__global__ void __launch_bounds__(384, 1) gru_rec(const float* __restrict__ Whh,
                                                  const float* __restrict__ bhh_g) {
    extern __shared__ float sm[];
    float* W_sh  = sm;                 // 48 rows x 260
    float* h_sh  = sm + 48 * 260;      // 8 rows x 260
    float* exA   = h_sh + 8 * 260;     // 2 x 128
    float* exHn  = exA + 256;          // 128
    float* exInn = exHn + 128;         // 128

    const int tid = threadIdx.x;
    const int ut  = blockIdx.x & 15;
    const int m   = blockIdx.x >> 4;
    const int g   = tid >> 7;          // 0..2
    const int r   = tid & 127;
    const int u   = r >> 3;            // 0..15
    const int b   = r & 7;             // 0..7
    const int ug  = ut * 16 + u;       // global hidden unit
    const int bg  = m * 8 + b;         // global batch

    // load W_hh tile (48 rows of 256) into SMEM, once
#pragma unroll
    for (int i = 0; i < 8; i++) {
        int f = tid + i * 384;         // 0..3071 float4 slots
        int row = f >> 6;              // 0..47 = gg*16+uu
        int kk = f & 63;
        int gg = row >> 4, uu = row & 15;
        float4 v = *(const float4*)&Whh[(size_t)(gg * DH + ut * 16 + uu) * DH + kk * 4];
        *(float4*)&W_sh[row * 260 + kk * 4] = v;
    }
    const float bhh = bhh_g[g * DH + ug];
    __syncthreads();

    const float* wrow = &W_sh[(g * 16 + u) * 260];
    const float* hrow = &h_sh[b * 260];

    for (int s = 0; s < SEQ; s++) {
        // gi is independent of h: issue early, hides behind spin + staging
        const float gival = __ldg(&g_gi[((size_t)s * BATCH + bg) * G3 + g * DH + ug]);

        if (s > 0) {
            if (tid == 0) {
                const unsigned target = (unsigned)(16 * s);
                unsigned v;
                do {
                    asm volatile("ld.global.acquire.gpu.u32 %0, [%1];"
                                 : "=r"(v) : "l"(&g_cnt[m]) : "memory");
                } while (v < target);
            }
            __syncthreads();
            const float* hsrc = &g_h[(s - 1) & 1][m * 8 * DH];
            for (int idx = tid; idx < 512; idx += 384) {   // 512 float4 = 8x256 floats
                int bb = idx >> 6, kk = idx & 63;
                float4 v = __ldcg((const float4*)&hsrc[bb * DH + kk * 4]); // bypass stale L1
                *(float4*)&h_sh[bb * 260 + kk * 4] = v;
            }
        } else {
            for (int idx = tid; idx < 512; idx += 384) {
                int bb = idx >> 6, kk = idx & 63;
                *(float4*)&h_sh[bb * 260 + kk * 4] = make_float4(0.f, 0.f, 0.f, 0.f);
            }
        }
        __syncthreads();

        // dot(h[b,:], W_hh[g*256+ug,:]) with packed f32x2 FMAs
        unsigned long long a0 = 0ull, a1 = 0ull;
#pragma unroll 16
        for (int kk = 0; kk < 64; kk++) {
            ulonglong2 hv = *(const ulonglong2*)&hrow[kk * 4];
            ulonglong2 wv = *(const ulonglong2*)&wrow[kk * 4];
            fma2(a0, hv.x, wv.x);
            fma2(a1, hv.y, wv.y);
        }
        float2 f0 = u2f2(a0), f1 = u2f2(a1);
        const float dot = (f0.x + f0.y) + (f1.x + f1.y);
        const float aval = dot + bhh;

        if (g < 2) exA[g * 128 + r] = aval + gival;   // Ar / Az
        else       { exHn[r] = aval; exInn[r] = gival; }
        __syncthreads();

        if (tid < 128) {
            const float Ar = exA[tid], Az = exA[128 + tid];
            const float hn = exHn[tid], inn = exInn[tid];
            const float rr = 1.0f / (1.0f + __expf(-Ar));
            const float zz = 1.0f / (1.0f + __expf(-Az));
            const float nn = tanhf(fmaf(rr, hn, inn));
            const float hold = h_sh[b * 260 + ug];    // zero at s==0
            const float hnew = (1.0f - zz) * nn + zz * hold;
            g_h[s & 1][bg * DH + ug] = hnew;
            g_outs[((size_t)s * BATCH + bg) * DH + ug] = hnew;
        }
        __threadfence();
        __syncthreads();
        if (tid == 0) atomicAdd(&g_cnt[m], 1u);
    }
}

// ---------------- Phase 3: attention ----------------
__global__ void k_scores(const float* __restrict__ watt) {
    __shared__ float wsm[DH];
    const int tid = threadIdx.x;
    wsm[tid] = watt[tid];   // blockDim = 256 = DH
    __syncthreads();
    const int s = blockIdx.x;
    const int w = tid >> 5, l = tid & 31;
    for (int bb = w; bb < BATCH; bb += 8) {
        const float* row = &g_outs[((size_t)s * BATCH + bb) * DH];
        float acc = 0.f;
#pragma unroll
        for (int k = l; k < DH; k += 32) acc = fmaf(row[k], wsm[k], acc);
#pragma unroll
        for (int o = 16; o > 0; o >>= 1) acc += __shfl_xor_sync(0xffffffffu, acc, o);
        if (l == 0) g_scores[s * BATCH + bb] = acc;
    }
}

__global__ void k_softmax() {
    __shared__ float red[256];
    const int b = blockIdx.x, tid = threadIdx.x;
    float mx = -1e30f;
    for (int s = tid; s < SEQ; s += 256) mx = fmaxf(mx, g_scores[s * BATCH + b]);
    red[tid] = mx; __syncthreads();
    for (int o = 128; o > 0; o >>= 1) { if (tid < o) red[tid] = fmaxf(red[tid], red[tid + o]); __syncthreads(); }
    mx = red[0]; __syncthreads();
    float sum = 0.f;
    for (int s = tid; s < SEQ; s += 256) sum += __expf(g_scores[s * BATCH + b] - mx);
    red[tid] = sum; __syncthreads();
    for (int o = 128; o > 0; o >>= 1) { if (tid < o) red[tid] += red[tid + o]; __syncthreads(); }
    const float inv = 1.0f / red[0];
    for (int s = tid; s < SEQ; s += 256)
        g_alpha[s * BATCH + b] = __expf(g_scores[s * BATCH + b] - mx) * inv;
}

__global__ void k_wsum(float* __restrict__ out) {
    const int b = blockIdx.x, h = threadIdx.x;
    float acc = 0.f;
#pragma unroll 4
    for (int s = 0; s < SEQ; s++)
        acc = fmaf(__ldg(&g_alpha[s * BATCH + b]),
                   g_outs[((size_t)s * BATCH + b) * DH + h], acc);
    out[b * DH + h] = acc;
}

// ---------------- launch ----------------
extern "C" void kernel_launch(void* const* d_in, const int* in_sizes, int n_in,
                              void* d_out, int out_size) {
    const float* data = (const float*)d_in[0];
    const float* Wih  = (const float*)d_in[1];
    const float* Whh  = (const float*)d_in[2];
    const float* bih  = (const float*)d_in[3];
    const float* bhh  = (const float*)d_in[4];
    const float* watt = (const float*)d_in[5];
    float* out = (float*)d_out;

    const int gi_smem  = 2 * 64 * 132 * (int)sizeof(float);              // 67584
    const int gru_smem = (48 * 260 + 8 * 260 + 256 + 128 + 128) * (int)sizeof(float); // 60288

    cudaFuncSetAttribute(gi_gemm, cudaFuncAttributeMaxDynamicSharedMemorySize, gi_smem);
    cudaFuncSetAttribute(gru_rec, cudaFuncAttributeMaxDynamicSharedMemorySize, gru_smem);

    k_init<<<1, 32>>>();
    dim3 gg(G3 / 64, (SEQ * BATCH) / 64);   // (12, 2048)
    gi_gemm<<<gg, 256, gi_smem>>>(data, Wih, bih);
    gru_rec<<<128, 384, gru_smem>>>(Whh, bhh);
    k_scores<<<SEQ, 256>>>(watt);
    k_softmax<<<BATCH, 256>>>();
    k_wsum<<<BATCH, 256>>>(out);
}

// round 2
// speedup vs baseline: 1.5426x; 1.5426x over previous
#include <cuda_runtime.h>
#include <cstdint>

#define SEQ   2048
#define BATCH 64
#define DIN   128
#define DH    256
#define G3    (3*DH)   // 768

// ---------------- scratch (device globals) ----------------
__device__ float g_gi[(size_t)SEQ * BATCH * G3];       // input gates
__device__ float g_outs[(size_t)SEQ * BATCH * DH];     // all hidden states
__device__ float g_h[2][BATCH * DH];                   // double-buffered h
__device__ float g_scorep[(size_t)SEQ * BATCH * 16];   // per-unit-tile score partials
__device__ float g_scores[SEQ * BATCH];
__device__ float g_wpart[8 * BATCH * DH];              // wsum partials
__device__ unsigned int g_cnt[8];                      // per batch-group counters

// ---------------- helpers ----------------
__device__ __forceinline__ void fma2(unsigned long long& acc,
                                     unsigned long long a,
                                     unsigned long long b) {
    asm volatile("fma.rn.f32x2 %0, %1, %2, %0;" : "+l"(acc) : "l"(a), "l"(b));
}
__device__ __forceinline__ float2 u2f2(unsigned long long v) {
    float2 f;
    asm("mov.b64 {%0, %1}, %2;" : "=f"(f.x), "=f"(f.y) : "l"(v));
    return f;
}

__global__ void k_init() {
    if (threadIdx.x < 8) g_cnt[threadIdx.x] = 0u;
}

// ---------------- Phase 1: GI = mask(data) @ W_ih^T + b_ih ----------------
// 128x128 block tile, 256 threads, 8x8 micro-tile (1B smem / FMA), K=128.
__global__ void __launch_bounds__(256, 1) gi_gemm(const float* __restrict__ X,
                                                  const float* __restrict__ Wih,
                                                  const float* __restrict__ bih) {
    extern __shared__ float sm[];
    float* As = sm;                // 128 x 132
    float* Bs = sm + 128 * 132;    // 128 x 132
    __shared__ unsigned char maskf[128];

    const int tid = threadIdx.x;
    const int n0 = blockIdx.x * 128;
    const int m0 = blockIdx.y * 128;

    if (tid < 128) maskf[tid] = (X[(size_t)(m0 + tid) * DIN + 127] > 0.0f) ? 1 : 0;
    __syncthreads();

#pragma unroll
    for (int it = 0; it < 16; it++) {
        int t = tid + it * 256;          // 0..4095 float4 slots
        int r = t >> 5, kk = t & 31;
        float4 va = *(const float4*)&X[(size_t)(m0 + r) * DIN + kk * 4];
        if (maskf[r] && kk >= 8 && kk < 16) va = make_float4(0.f, 0.f, 0.f, 0.f);
        *(float4*)&As[r * 132 + kk * 4] = va;
        float4 vb = *(const float4*)&Wih[(size_t)(n0 + r) * DIN + kk * 4];
        *(float4*)&Bs[r * 132 + kk * 4] = vb;
    }
    __syncthreads();

    const int tx = tid & 15;   // col group
    const int ty = tid >> 4;   // row group

    unsigned long long acc[8][8];
#pragma unroll
    for (int i = 0; i < 8; i++)
#pragma unroll
        for (int j = 0; j < 8; j++) acc[i][j] = 0ull;

#pragma unroll 8
    for (int p = 0; p < 64; p++) {     // k-pairs
        unsigned long long av[8], bv[8];
#pragma unroll
        for (int i = 0; i < 8; i++)
            av[i] = *(const unsigned long long*)&As[(ty + 16 * i) * 132 + 2 * p];
#pragma unroll
        for (int j = 0; j < 8; j++)
            bv[j] = *(const unsigned long long*)&Bs[(tx + 16 * j) * 132 + 2 * p];
#pragma unroll
        for (int i = 0; i < 8; i++)
#pragma unroll
            for (int j = 0; j < 8; j++) fma2(acc[i][j], av[i], bv[j]);
    }

    __syncthreads();                   // done reading As/Bs
#pragma unroll
    for (int i = 0; i < 8; i++)
#pragma unroll
        for (int j = 0; j < 8; j++) {
            float2 f = u2f2(acc[i][j]);
            As[(ty + 16 * i) * 132 + tx + 16 * j] = f.x + f.y;   // stage C in As
        }
    __syncthreads();

#pragma unroll
    for (int it = 0; it < 16; it++) {
        int t = tid + it * 256;
        int r = t >> 5, kk = t & 31;
        float4 c = *(const float4*)&As[r * 132 + kk * 4];
        float4 b = *(const float4*)&bih[n0 + kk * 4];
        c.x += b.x; c.y += b.y; c.z += b.z; c.w += b.w;
        *(float4*)&g_gi[(size_t)(m0 + r) * G3 + n0 + kk * 4] = c;
    }
}

// ---------------- Phase 2: persistent GRU recurrence ----------------
// 128 blocks = 8 batch-groups x 16 unit-tiles (16 units = 48 gate rows).
// 256 threads: 16 k-chunks x (4 batch x 6 row) register tiles + split-K smem reduce.
__global__ void __launch_bounds__(256, 1) gru_rec(const float* __restrict__ Whh,
                                                  const float* __restrict__ bhh_g,
                                                  const float* __restrict__ watt) {
    extern __shared__ float sm[];
    float* W_sh = sm;                   // 48 x 260
    float* h_sh = sm + 48 * 260;        // 8  x 260
    float* part = h_sh + 8 * 260;       // 384 x 17
    float* Ared = part + 384 * 17;      // 384

    const int tid = threadIdx.x;
    const int ut  = blockIdx.x & 15;
    const int m   = blockIdx.x >> 4;
    const int kc  = tid >> 4;           // 0..15 k-chunk
    const int ot  = tid & 15;
    const int bq  = ot >> 3;            // 0..1
    const int rq  = ot & 7;             // 0..7
    const int kbase = kc * 16;

    // epilogue identity (tid < 128)
    const int eb = tid >> 4;            // local batch 0..7
    const int eu = tid & 15;            // unit 0..15
    const int ug = ut * 16 + eu;
    const int bg = m * 8 + eb;

    // load W_hh tile once: local row r = g*16 + u  ->  global row g*256 + ut*16 + u
#pragma unroll
    for (int it = 0; it < 12; it++) {
        int t = tid + it * 256;          // 0..3071 float4 slots
        int row = t >> 6, kk = t & 63;
        int g = row >> 4, uu = row & 15;
        float4 v = *(const float4*)&Whh[(size_t)(g * DH + ut * 16 + uu) * DH + kk * 4];
        *(float4*)&W_sh[row * 260 + kk * 4] = v;
    }
    float bhh0 = 0.f, bhh1 = 0.f, bhh2 = 0.f, wattv = 0.f;
    if (tid < 128) {
        bhh0 = bhh_g[0 * DH + ug];
        bhh1 = bhh_g[1 * DH + ug];
        bhh2 = bhh_g[2 * DH + ug];
        wattv = watt[ug];
    }
    __syncthreads();

    for (int s = 0; s < SEQ; s++) {
        // prefetch gi (independent of h)
        float gir = 0.f, giz = 0.f, gin = 0.f;
        if (tid < 128) {
            const size_t base = ((size_t)s * BATCH + bg) * G3 + ug;
            gir = __ldcg(&g_gi[base]);
            giz = __ldcg(&g_gi[base + DH]);
            gin = __ldcg(&g_gi[base + 2 * DH]);
        }

        if (s > 0) {
            if (tid == 0) {
                const unsigned target = (unsigned)(16 * s);
                unsigned v;
                do {
                    asm volatile("ld.global.acquire.gpu.u32 %0, [%1];"
                                 : "=r"(v) : "l"(&g_cnt[m]) : "memory");
                } while (v < target);
            }
            __syncthreads();
            const float* hsrc = &g_h[(s - 1) & 1][m * 8 * DH];
#pragma unroll
            for (int it = 0; it < 2; it++) {
                int idx = tid + it * 256;    // 512 float4
                int bb = idx >> 6, kk = idx & 63;
                float4 v = __ldcg((const float4*)&hsrc[bb * DH + kk * 4]);
                *(float4*)&h_sh[bb * 260 + kk * 4] = v;
            }
        } else {
#pragma unroll
            for (int it = 0; it < 2; it++) {
                int idx = tid + it * 256;
                int bb = idx >> 6, kk = idx & 63;
                *(float4*)&h_sh[bb * 260 + kk * 4] = make_float4(0.f, 0.f, 0.f, 0.f);
            }
        }
        __syncthreads();

        // C[b][r] partial over k-chunk: 4 batches (bq+2i) x 6 rows (rq+8j) x 16 k
        unsigned long long acc[4][6];
#pragma unroll
        for (int i = 0; i < 4; i++)
#pragma unroll
            for (int j = 0; j < 6; j++) acc[i][j] = 0ull;

#pragma unroll
        for (int q = 0; q < 4; q++) {
            ulonglong2 hq[4], wq[6];
#pragma unroll
            for (int i = 0; i < 4; i++)
                hq[i] = *(const ulonglong2*)&h_sh[(bq + 2 * i) * 260 + kbase + q * 4];
#pragma unroll
            for (int j = 0; j < 6; j++)
                wq[j] = *(const ulonglong2*)&W_sh[(rq + 8 * j) * 260 + kbase + q * 4];
#pragma unroll
            for (int i = 0; i < 4; i++)
#pragma unroll
                for (int j = 0; j < 6; j++) {
                    fma2(acc[i][j], hq[i].x, wq[j].x);
                    fma2(acc[i][j], hq[i].y, wq[j].y);
                }
        }

#pragma unroll
        for (int i = 0; i < 4; i++)
#pragma unroll
            for (int j = 0; j < 6; j++) {
                float2 f = u2f2(acc[i][j]);
                int o = (bq + 2 * i) * 48 + (rq + 8 * j);
                part[o * 17 + kc] = f.x + f.y;
            }
        __syncthreads();

        // split-K gather reduce: 384 outputs
#pragma unroll
        for (int o = tid; o < 384; o += 256) {
            float ssum = 0.f;
#pragma unroll
            for (int c = 0; c < 16; c++) ssum += part[o * 17 + c];
            Ared[o] = ssum;
        }
        __syncthreads();

        if (tid < 128) {
            const float Ar = Ared[eb * 48 + eu]      + bhh0 + gir;
            const float Az = Ared[eb * 48 + 16 + eu] + bhh1 + giz;
            const float An = Ared[eb * 48 + 32 + eu] + bhh2;
            const float rr = 1.0f / (1.0f + __expf(-Ar));
            const float zz = 1.0f / (1.0f + __expf(-Az));
            const float nn = tanhf(fmaf(rr, An, gin));
            const float hold = h_sh[eb * 260 + ug];
            const float hnew = fmaf(zz, hold - nn, nn);
            __stcg(&g_h[s & 1][bg * DH + ug], hnew);
            g_outs[((size_t)s * BATCH + bg) * DH + ug] = hnew;
            // fused score partial: reduce over 16 units
            float sc = hnew * wattv;
#pragma unroll
            for (int o = 8; o > 0; o >>= 1) sc += __shfl_xor_sync(0xffffffffu, sc, o);
            if (eu == 0) g_scorep[((size_t)s * BATCH + bg) * 16 + ut] = sc;
        }
        __syncthreads();
        if (tid == 0) {
            unsigned one = 1u;
            asm volatile("red.release.gpu.global.add.u32 [%0], %1;"
                         :: "l"(&g_cnt[m]), "r"(one) : "memory");
        }
    }
}

// ---------------- Phase 3: attention ----------------
__global__ void k_scores_red() {
    const int idx = blockIdx.x * 256 + threadIdx.x;   // (s*64+b), 131072 total
    const float4* p = (const float4*)&g_scorep[(size_t)idx * 16];
    float4 a = p[0], b = p[1], c = p[2], d = p[3];
    g_scores[idx] = (a.x + a.y + a.z + a.w) + (b.x + b.y + b.z + b.w) +
                    (c.x + c.y + c.z + c.w) + (d.x + d.y + d.z + d.w);
}

__global__ void k_softmax() {
    __shared__ float red[256];
    const int b = blockIdx.x, tid = threadIdx.x;
    float mx = -1e30f;
    for (int s = tid; s < SEQ; s += 256) mx = fmaxf(mx, g_scores[s * BATCH + b]);
    red[tid] = mx; __syncthreads();
    for (int o = 128; o > 0; o >>= 1) { if (tid < o) red[tid] = fmaxf(red[tid], red[tid + o]); __syncthreads(); }
    mx = red[0]; __syncthreads();
    float sum = 0.f;
    for (int s = tid; s < SEQ; s += 256) sum += __expf(g_scores[s * BATCH + b] - mx);
    red[tid] = sum; __syncthreads();
    for (int o = 128; o > 0; o >>= 1) { if (tid < o) red[tid] += red[tid + o]; __syncthreads(); }
    const float inv = 1.0f / red[0];
    for (int s = tid; s < SEQ; s += 256)
        g_scores[s * BATCH + b] = __expf(g_scores[s * BATCH + b] - mx) * inv;  // alpha in-place
}

__global__ void k_wsum1() {
    const int b = blockIdx.x, c = blockIdx.y, h = threadIdx.x;
    float acc = 0.f;
    const int s0 = c * 256;
#pragma unroll 4
    for (int s = s0; s < s0 + 256; s++)
        acc = fmaf(__ldg(&g_scores[s * BATCH + b]),
                   g_outs[((size_t)s * BATCH + b) * DH + h], acc);
    g_wpart[(c * BATCH + b) * DH + h] = acc;
}

__global__ void k_wsum2(float* __restrict__ out) {
    const int b = blockIdx.x, h = threadIdx.x;
    float acc = 0.f;
#pragma unroll
    for (int c = 0; c < 8; c++) acc += g_wpart[(c * BATCH + b) * DH + h];
    out[b * DH + h] = acc;
}

// ---------------- launch ----------------
extern "C" void kernel_launch(void* const* d_in, const int* in_sizes, int n_in,
                              void* d_out, int out_size) {
    const float* data = (const float*)d_in[0];
    const float* Wih  = (const float*)d_in[1];
    const float* Whh  = (const float*)d_in[2];
    const float* bih  = (const float*)d_in[3];
    const float* bhh  = (const float*)d_in[4];
    const float* watt = (const float*)d_in[5];
    float* out = (float*)d_out;

    const int gi_smem  = 2 * 128 * 132 * (int)sizeof(float);                     // 135168
    const int gru_smem = (48 * 260 + 8 * 260 + 384 * 17 + 384) * (int)sizeof(float); // 85888

    cudaFuncSetAttribute(gi_gemm, cudaFuncAttributeMaxDynamicSharedMemorySize, gi_smem);
    cudaFuncSetAttribute(gru_rec, cudaFuncAttributeMaxDynamicSharedMemorySize, gru_smem);

    k_init<<<1, 32>>>();
    dim3 gg(G3 / 128, (SEQ * BATCH) / 128);   // (6, 1024)
    gi_gemm<<<gg, 256, gi_smem>>>(data, Wih, bih);
    gru_rec<<<128, 256, gru_smem>>>(Whh, bhh, watt);
    k_scores_red<<<(SEQ * BATCH) / 256, 256>>>();
    k_softmax<<<BATCH, 256>>>();
    dim3 gw(BATCH, 8);
    k_wsum1<<<gw, 256>>>();
    k_wsum2<<<BATCH, 256>>>(out);
}